// round 2
// baseline (speedup 1.0000x reference)
#include <cuda_runtime.h>
#include <math.h>
#include <stdint.h>

#define Tn 1024
#define Bn 256

// ---------------- static device scratch ----------------
__device__ __align__(128) float g_pv[46 * 3 * 256];
__device__ __align__(128) float g_pa[16 * 3 * 256];
__device__ __align__(128) float g_pb[256 * 3 * 256];
__device__ __align__(128) float g_Wihc[768 * 256];
__device__ __align__(128) float g_u[768];
__device__ __align__(128) float g_h[(size_t)262144 * 256];
__device__ __align__(128) float g_gi[(size_t)262144 * 768];
__device__ __align__(128) float g_hid[2][256 * 256];

__device__ __forceinline__ float sigm(float x) { return 1.f / (1.f + expf(-x)); }

// ---------------- K0: projection tables ----------------
__global__ void k_pv(const float* __restrict__ ph, const float* __restrict__ w) {
    int p = blockIdx.x, k = blockIdx.y, c = threadIdx.x;
    float a = 0.f;
#pragma unroll 8
    for (int e = 0; e < 64; e++) a = fmaf(ph[p * 64 + e], w[c * 396 + e * 3 + k], a);
    g_pv[(p * 3 + k) * 256 + c] = a;
}
__global__ void k_pa(const float* __restrict__ w) {
    int m = blockIdx.x, k = blockIdx.y, c = threadIdx.x;
    float a = 0.f;
#pragma unroll
    for (int bit = 0; bit < 4; bit++)
        if ((m >> bit) & 1) a += w[c * 396 + (64 + bit) * 3 + k];
    g_pa[(m * 3 + k) * 256 + c] = a;
}
__global__ void k_pb(const int* __restrict__ sid, const float* __restrict__ st,
                     const float* __restrict__ w) {
    int b = blockIdx.x, k = blockIdx.y, c = threadIdx.x;
    int s0 = sid[b];
    float a = 0.f;
#pragma unroll 8
    for (int s = 0; s < 64; s++) a = fmaf(st[s0 * 64 + s], w[c * 396 + (68 + s) * 3 + k], a);
    g_pb[(b * 3 + k) * 256 + c] = a;
}
__global__ void k_wih(const float* __restrict__ Wih) {
    int g = blockIdx.x;
    g_Wihc[g * 256 + threadIdx.x] = Wih[g * 257 + threadIdx.x];
    if (threadIdx.x == 0) g_u[g] = Wih[g * 257 + 256];
}

// ---------------- K1: encoder ----------------
__global__ void k_enc(const int* __restrict__ vw, const int* __restrict__ cs,
                      const int* __restrict__ sa, const int* __restrict__ ea,
                      const int* __restrict__ sap, const int* __restrict__ eap,
                      const float* __restrict__ encb) {
    int t = blockIdx.x, b = blockIdx.y, c = threadIdx.x;
    float a = encb[c];
#pragma unroll
    for (int k = 0; k < 3; k++) {
        int tp = t + k - 1;
        if (tp < 0 || tp >= Tn) continue;
        int o = b * Tn + tp;
        int iv = vw[o] + 1;
        int ic = cs[o] + 1;
        int ia = sa[o] + 2 * ea[o] + 4 * sap[o] + 8 * eap[o];
        a += g_pv[(iv * 3 + k) * 256 + c] + g_pv[(ic * 3 + k) * 256 + c] +
             g_pa[(ia * 3 + k) * 256 + c] + g_pb[(b * 3 + k) * 256 + c];
    }
    g_h[((size_t)(t * 256 + b)) * 256 + c] = fmaxf(a, 0.f);
}

// ---------------- K2: gi GEMM (M=262144, N=768, K=256) ----------------
__global__ __launch_bounds__(256) void k_gemm_gi(const float* __restrict__ bih,
                                                 const float* __restrict__ bhh) {
    __shared__ float As[16][68];
    __shared__ float Bs[16][68];
    int n0 = blockIdx.x * 64, m0 = blockIdx.y * 64;
    int tid = threadIdx.x;
    int lr = tid >> 2, kq = tid & 3;
    float acc[4][4] = {};
    const float* Aptr = g_h + (size_t)(m0 + lr) * 256 + kq * 4;
    const float* Bptr = g_Wihc + (size_t)(n0 + lr) * 256 + kq * 4;
    int r0 = (tid >> 4) * 4, c0 = (tid & 15) * 4;
    for (int kt = 0; kt < 256; kt += 16) {
        float4 av = *(const float4*)(Aptr + kt);
        float4 bv = *(const float4*)(Bptr + kt);
        As[kq * 4 + 0][lr] = av.x; As[kq * 4 + 1][lr] = av.y;
        As[kq * 4 + 2][lr] = av.z; As[kq * 4 + 3][lr] = av.w;
        Bs[kq * 4 + 0][lr] = bv.x; Bs[kq * 4 + 1][lr] = bv.y;
        Bs[kq * 4 + 2][lr] = bv.z; Bs[kq * 4 + 3][lr] = bv.w;
        __syncthreads();
#pragma unroll
        for (int k = 0; k < 16; k++) {
            float4 a4 = *(const float4*)&As[k][r0];
            float4 b4 = *(const float4*)&Bs[k][c0];
            float ax[4] = {a4.x, a4.y, a4.z, a4.w};
            float bx[4] = {b4.x, b4.y, b4.z, b4.w};
#pragma unroll
            for (int i = 0; i < 4; i++)
#pragma unroll
                for (int j = 0; j < 4; j++) acc[i][j] = fmaf(ax[i], bx[j], acc[i][j]);
        }
        __syncthreads();
    }
    float bias[4];
#pragma unroll
    for (int j = 0; j < 4; j++) {
        int n = n0 + c0 + j;
        bias[j] = bih[n] + (n < 512 ? bhh[n] : 0.f);
    }
#pragma unroll
    for (int i = 0; i < 4; i++) {
        float4 o;
        o.x = acc[i][0] + bias[0]; o.y = acc[i][1] + bias[1];
        o.z = acc[i][2] + bias[2]; o.w = acc[i][3] + bias[3];
        *(float4*)&g_gi[((size_t)(m0 + r0 + i)) * 768 + n0 + c0] = o;
    }
}

// ---------------- K3: persistent GRU (16 clusters x 8 CTAs) ----------------
#define SMEM3_BYTES ((96 * 260 + 16 * 260 + 256) * 4)

__device__ __forceinline__ float dot4(float4 h, float4 w, float a) {
    a = fmaf(h.x, w.x, a); a = fmaf(h.y, w.y, a);
    a = fmaf(h.z, w.z, a); return fmaf(h.w, w.w, a);
}

__global__ void __cluster_dims__(8, 1, 1) __launch_bounds__(256, 1)
k_gru(const float* __restrict__ hid0, const float* __restrict__ Whh,
      const float* __restrict__ bhh, const float* __restrict__ pw,
      const float* __restrict__ pb, float* __restrict__ out) {
    extern __shared__ float sm[];
    float* Ws = sm;                           // [96][260]
    float* hsm = sm + 96 * 260;               // [16][260]
    float* pws = sm + 96 * 260 + 16 * 260;    // [256]
    __shared__ float f0_s[16];

    int tid = threadIdx.x;
    int cid = blockIdx.x >> 3, rank = blockIdx.x & 7;
    int b0 = cid * 16, j0 = rank * 32;
    int w = tid >> 5, l = tid & 31, bl = l & 15, jsel = l >> 4;
    int jbase = w * 4 + jsel * 2;
    int jg0 = j0 + jbase;

    for (int idx = tid; idx < 96 * 64; idx += 256) {
        int row = idx >> 6, kq = idx & 63;
        int gate = row >> 5, jloc = row & 31;
        *(float4*)&Ws[row * 260 + kq * 4] =
            *(const float4*)&Whh[((size_t)(gate * 256 + j0 + jloc)) * 256 + kq * 4];
    }
    {
        int sb = tid >> 4, sk = (tid & 15) * 16;
#pragma unroll
        for (int i = 0; i < 4; i++)
            *(float4*)&hsm[sb * 260 + sk + i * 4] =
                *(const float4*)&hid0[(size_t)(b0 + sb) * 256 + sk + i * 4];
    }
    if (tid < 16) f0_s[tid] = 0.f;
    pws[tid] = pw[tid];

    float uR0 = g_u[jg0], uR1 = g_u[jg0 + 1];
    float uZ0 = g_u[256 + jg0], uZ1 = g_u[256 + jg0 + 1];
    float uN0 = g_u[512 + jg0], uN1 = g_u[512 + jg0 + 1];
    float bN0 = bhh[512 + jg0], bN1 = bhh[512 + jg0 + 1];
    float postb = pb[0];
    __syncthreads();

    const float* WsR = Ws + jbase * 260;
    const float* WsZ = Ws + (32 + jbase) * 260;
    const float* WsN = Ws + (64 + jbase) * 260;
    const float* hb = hsm + bl * 260;

    for (int t = 0; t < Tn; t++) {
        const float* gib = g_gi + ((size_t)t * 256 + b0 + bl) * 768;
        float giR0 = gib[jg0], giR1 = gib[jg0 + 1];
        float giZ0 = gib[256 + jg0], giZ1 = gib[256 + jg0 + 1];
        float giN0 = gib[512 + jg0], giN1 = gib[512 + jg0 + 1];

        float aR0 = 0, aR1 = 0, aZ0 = 0, aZ1 = 0, aN0 = 0, aN1 = 0;
#pragma unroll 4
        for (int kq = 0; kq < 64; kq++) {
            float4 hv = *(const float4*)(hb + kq * 4);
            aR0 = dot4(hv, *(const float4*)(WsR + kq * 4), aR0);
            aR1 = dot4(hv, *(const float4*)(WsR + 260 + kq * 4), aR1);
            aZ0 = dot4(hv, *(const float4*)(WsZ + kq * 4), aZ0);
            aZ1 = dot4(hv, *(const float4*)(WsZ + 260 + kq * 4), aZ1);
            aN0 = dot4(hv, *(const float4*)(WsN + kq * 4), aN0);
            aN1 = dot4(hv, *(const float4*)(WsN + 260 + kq * 4), aN1);
        }
        float f0 = f0_s[bl];
        float h0 = hb[jg0], h1 = hb[jg0 + 1];
        float r0 = sigm(fmaf(uR0, f0, giR0) + aR0);
        float r1 = sigm(fmaf(uR1, f0, giR1) + aR1);
        float z0 = sigm(fmaf(uZ0, f0, giZ0) + aZ0);
        float z1 = sigm(fmaf(uZ1, f0, giZ1) + aZ1);
        float n0 = tanhf(fmaf(uN0, f0, giN0) + r0 * (aN0 + bN0));
        float n1 = tanhf(fmaf(uN1, f0, giN1) + r1 * (aN1 + bN1));
        float hn0 = (1.f - z0) * n0 + z0 * h0;
        float hn1 = (1.f - z1) * n1 + z1 * h1;

        int buf = t & 1;
        __stcg(&g_hid[buf][(b0 + bl) * 256 + jg0], hn0);
        __stcg(&g_hid[buf][(b0 + bl) * 256 + jg0 + 1], hn1);

        asm volatile("barrier.cluster.arrive.aligned;\n" ::: "memory");
        asm volatile("barrier.cluster.wait.aligned;\n" ::: "memory");

        {
            int sb = tid >> 4, sk = (tid & 15) * 16;
            const float4* src = (const float4*)&g_hid[buf][(b0 + sb) * 256 + sk];
#pragma unroll
            for (int i = 0; i < 4; i++)
                *(float4*)&hsm[sb * 260 + sk + i * 4] = __ldcg(src + i);
        }
        __syncthreads();

        // f0 = hid_new @ post_w + post_b (warp w handles batches 2w, 2w+1)
#pragma unroll
        for (int q = 0; q < 2; q++) {
            int b = 2 * w + q;
            float p = 0.f;
#pragma unroll
            for (int i = 0; i < 8; i++)
                p = fmaf(hsm[b * 260 + l * 8 + i], pws[l * 8 + i], p);
#pragma unroll
            for (int o = 16; o; o >>= 1) p += __shfl_xor_sync(0xFFFFFFFFu, p, o);
            if (l == 0) {
                float f = p + postb;
                f0_s[b] = f;
                out[(size_t)(b0 + b) * Tn + t] = f;
            }
        }
        __syncthreads();
    }
}

// ---------------- launcher ----------------
extern "C" void kernel_launch(void* const* d_in, const int* in_sizes, int n_in,
                              void* d_out, int out_size) {
    int off = (n_in >= 19) ? 1 : 0;
    const int* vw   = (const int*)d_in[off + 0];
    const int* cs   = (const int*)d_in[off + 1];
    const int* sa   = (const int*)d_in[off + 2];
    const int* ea   = (const int*)d_in[off + 3];
    const int* sap  = (const int*)d_in[off + 4];
    const int* eap  = (const int*)d_in[off + 5];
    const int* sid  = (const int*)d_in[off + 6];
    const float* hid0 = (const float*)d_in[off + 7];
    const float* pht  = (const float*)d_in[off + 8];
    const float* spt  = (const float*)d_in[off + 9];
    const float* encw = (const float*)d_in[off + 10];
    const float* encb = (const float*)d_in[off + 11];
    const float* Wih  = (const float*)d_in[off + 12];
    const float* Whh  = (const float*)d_in[off + 13];
    const float* bih  = (const float*)d_in[off + 14];
    const float* bhh  = (const float*)d_in[off + 15];
    const float* pw   = (const float*)d_in[off + 16];
    const float* pb   = (const float*)d_in[off + 17];
    float* out = (float*)d_out;

    k_pv<<<dim3(46, 3), 256>>>(pht, encw);
    k_pa<<<dim3(16, 3), 256>>>(encw);
    k_pb<<<dim3(256, 3), 256>>>(sid, spt, encw);
    k_wih<<<768, 256>>>(Wih);
    k_enc<<<dim3(Tn, Bn), 256>>>(vw, cs, sa, ea, sap, eap, encb);
    k_gemm_gi<<<dim3(12, 4096), 256>>>(bih, bhh);

    static int smem_set = 0;
    if (!smem_set) {
        cudaFuncSetAttribute(k_gru, cudaFuncAttributeMaxDynamicSharedMemorySize, SMEM3_BYTES);
        smem_set = 1;
    }
    k_gru<<<128, 256, SMEM3_BYTES>>>(hid0, Whh, bhh, pw, pb, out);
}

// round 3
// speedup vs baseline: 1.0114x; 1.0114x over previous
#include <cuda_runtime.h>
#include <math.h>
#include <stdint.h>

#define Tn 1024
#define Bn 256

typedef unsigned long long ull;

// ---------------- static device scratch ----------------
__device__ __align__(128) float g_pv[46 * 3 * 256];
__device__ __align__(128) float g_pa[16 * 3 * 256];
__device__ __align__(128) float g_pb[256 * 3 * 256];
__device__ __align__(128) float g_Wihc[768 * 256];
__device__ __align__(128) float g_u[768];
__device__ __align__(128) float g_h[(size_t)262144 * 256];
__device__ __align__(128) float g_gi[(size_t)262144 * 768];
__device__ __align__(128) float g_hid[2][256 * 256];

__device__ __forceinline__ float sigm(float x) { return 1.f / (1.f + expf(-x)); }

// ---- packed f32x2 helpers (sm_100a FFMA2 path) ----
__device__ __forceinline__ ull pk2(float x, float y) {
    ull r; asm("mov.b64 %0, {%1,%2};" : "=l"(r) : "f"(x), "f"(y)); return r;
}
__device__ __forceinline__ void upk2(ull v, float& x, float& y) {
    asm("mov.b64 {%0,%1}, %2;" : "=f"(x), "=f"(y) : "l"(v));
}
__device__ __forceinline__ ull fma2(ull a, ull b, ull c) {
    ull d; asm("fma.rn.f32x2 %0, %1, %2, %3;" : "=l"(d) : "l"(a), "l"(b), "l"(c)); return d;
}

// ---------------- K0: projection tables ----------------
__global__ void k_pv(const float* __restrict__ ph, const float* __restrict__ w) {
    int p = blockIdx.x, k = blockIdx.y, c = threadIdx.x;
    float a = 0.f;
#pragma unroll 8
    for (int e = 0; e < 64; e++) a = fmaf(ph[p * 64 + e], w[c * 396 + e * 3 + k], a);
    g_pv[(p * 3 + k) * 256 + c] = a;
}
__global__ void k_pa(const float* __restrict__ w) {
    int m = blockIdx.x, k = blockIdx.y, c = threadIdx.x;
    float a = 0.f;
#pragma unroll
    for (int bit = 0; bit < 4; bit++)
        if ((m >> bit) & 1) a += w[c * 396 + (64 + bit) * 3 + k];
    g_pa[(m * 3 + k) * 256 + c] = a;
}
__global__ void k_pb(const int* __restrict__ sid, const float* __restrict__ st,
                     const float* __restrict__ w) {
    int b = blockIdx.x, k = blockIdx.y, c = threadIdx.x;
    int s0 = sid[b];
    float a = 0.f;
#pragma unroll 8
    for (int s = 0; s < 64; s++) a = fmaf(st[s0 * 64 + s], w[c * 396 + (68 + s) * 3 + k], a);
    g_pb[(b * 3 + k) * 256 + c] = a;
}
__global__ void k_wih(const float* __restrict__ Wih) {
    int g = blockIdx.x;
    g_Wihc[g * 256 + threadIdx.x] = Wih[g * 257 + threadIdx.x];
    if (threadIdx.x == 0) g_u[g] = Wih[g * 257 + 256];
}

// ---------------- K1: encoder ----------------
__global__ void k_enc(const int* __restrict__ vw, const int* __restrict__ cs,
                      const int* __restrict__ sa, const int* __restrict__ ea,
                      const int* __restrict__ sap, const int* __restrict__ eap,
                      const float* __restrict__ encb) {
    int t = blockIdx.x, b = blockIdx.y, c = threadIdx.x;
    float a = encb[c];
#pragma unroll
    for (int k = 0; k < 3; k++) {
        int tp = t + k - 1;
        if (tp < 0 || tp >= Tn) continue;
        int o = b * Tn + tp;
        int iv = vw[o] + 1;
        int ic = cs[o] + 1;
        int ia = sa[o] + 2 * ea[o] + 4 * sap[o] + 8 * eap[o];
        a += g_pv[(iv * 3 + k) * 256 + c] + g_pv[(ic * 3 + k) * 256 + c] +
             g_pa[(ia * 3 + k) * 256 + c] + g_pb[(b * 3 + k) * 256 + c];
    }
    g_h[((size_t)(t * 256 + b)) * 256 + c] = fmaxf(a, 0.f);
}

// ---------------- K2: gi GEMM (M=262144, N=768, K=256), f32x2-packed ----------------
__global__ __launch_bounds__(256) void k_gemm_gi(const float* __restrict__ bih,
                                                 const float* __restrict__ bhh) {
    __shared__ float As[16][68];
    __shared__ float Bs[16][68];
    int n0 = blockIdx.x * 64, m0 = blockIdx.y * 64;
    int tid = threadIdx.x;
    int lr = tid >> 2, kq = tid & 3;
    ull acc[4][2];
#pragma unroll
    for (int i = 0; i < 4; i++) { acc[i][0] = 0ULL; acc[i][1] = 0ULL; }
    const float* Aptr = g_h + (size_t)(m0 + lr) * 256 + kq * 4;
    const float* Bptr = g_Wihc + (size_t)(n0 + lr) * 256 + kq * 4;
    int r0 = (tid >> 4) * 4, c0 = (tid & 15) * 4;
    for (int kt = 0; kt < 256; kt += 16) {
        float4 av = *(const float4*)(Aptr + kt);
        float4 bv = *(const float4*)(Bptr + kt);
        As[kq * 4 + 0][lr] = av.x; As[kq * 4 + 1][lr] = av.y;
        As[kq * 4 + 2][lr] = av.z; As[kq * 4 + 3][lr] = av.w;
        Bs[kq * 4 + 0][lr] = bv.x; Bs[kq * 4 + 1][lr] = bv.y;
        Bs[kq * 4 + 2][lr] = bv.z; Bs[kq * 4 + 3][lr] = bv.w;
        __syncthreads();
#pragma unroll
        for (int k = 0; k < 16; k++) {
            float4 a4 = *(const float4*)&As[k][r0];
            ulonglong2 bp = *(const ulonglong2*)&Bs[k][c0];  // (c0,c0+1),(c0+2,c0+3)
            ull a0 = pk2(a4.x, a4.x), a1 = pk2(a4.y, a4.y);
            ull a2 = pk2(a4.z, a4.z), a3 = pk2(a4.w, a4.w);
            acc[0][0] = fma2(a0, bp.x, acc[0][0]); acc[0][1] = fma2(a0, bp.y, acc[0][1]);
            acc[1][0] = fma2(a1, bp.x, acc[1][0]); acc[1][1] = fma2(a1, bp.y, acc[1][1]);
            acc[2][0] = fma2(a2, bp.x, acc[2][0]); acc[2][1] = fma2(a2, bp.y, acc[2][1]);
            acc[3][0] = fma2(a3, bp.x, acc[3][0]); acc[3][1] = fma2(a3, bp.y, acc[3][1]);
        }
        __syncthreads();
    }
    float bias[4];
#pragma unroll
    for (int j = 0; j < 4; j++) {
        int n = n0 + c0 + j;
        bias[j] = bih[n] + (n < 512 ? bhh[n] : 0.f);
    }
#pragma unroll
    for (int i = 0; i < 4; i++) {
        float v0, v1, v2, v3;
        upk2(acc[i][0], v0, v1);
        upk2(acc[i][1], v2, v3);
        float4 o;
        o.x = v0 + bias[0]; o.y = v1 + bias[1];
        o.z = v2 + bias[2]; o.w = v3 + bias[3];
        *(float4*)&g_gi[((size_t)(m0 + r0 + i)) * 768 + n0 + c0] = o;
    }
}

// ---------------- K3: persistent GRU (16 clusters x 8 CTAs), f32x2-packed ----------------
// SMEM: Ws2 = 48 pair-rows x 256 float2 (stride 258) | hsm 16x260 f | pws 256 f
#define WS2_F2_STRIDE 258
#define HSM_OFF (48 * WS2_F2_STRIDE * 2)          // floats
#define PWS_OFF (HSM_OFF + 16 * 260)
#define SMEM3_BYTES ((PWS_OFF + 256) * 4)

__global__ void __cluster_dims__(8, 1, 1) __launch_bounds__(256, 1)
k_gru(const float* __restrict__ hid0, const float* __restrict__ Whh,
      const float* __restrict__ bhh, const float* __restrict__ pw,
      const float* __restrict__ pb, float* __restrict__ out) {
    extern __shared__ float sm[];
    float2* Ws2 = (float2*)sm;                 // [48][258]
    float* hsm = sm + HSM_OFF;                 // [16][260]
    float* pws = sm + PWS_OFF;                 // [256]
    __shared__ float f0_s[16];

    int tid = threadIdx.x;
    int cid = blockIdx.x >> 3, rank = blockIdx.x & 7;
    int b0 = cid * 16, j0 = rank * 32;
    int w = tid >> 5, l = tid & 31, bl = l & 15, jsel = l >> 4;
    int p = w * 2 + jsel;          // pair index 0..15
    int jg0 = j0 + 2 * p;          // two output columns jg0, jg0+1

    // load W_hh slice as column-pair-interleaved float2:
    // Ws2[gate*16 + pp][k] = (Whh[gate*256+j0+2pp][k], Whh[gate*256+j0+2pp+1][k])
    for (int idx = tid; idx < 48 * 256; idx += 256) {
        int prow = idx >> 8, k = idx & 255;
        int gate = prow / 16, pp = prow % 16;
        size_t r0 = ((size_t)(gate * 256 + j0 + 2 * pp)) * 256 + k;
        float2 v;
        v.x = Whh[r0];
        v.y = Whh[r0 + 256];
        Ws2[prow * WS2_F2_STRIDE + k] = v;
    }
    {
        int sb = tid >> 4, sk = (tid & 15) * 16;
#pragma unroll
        for (int i = 0; i < 4; i++)
            *(float4*)&hsm[sb * 260 + sk + i * 4] =
                *(const float4*)&hid0[(size_t)(b0 + sb) * 256 + sk + i * 4];
    }
    if (tid < 16) f0_s[tid] = 0.f;
    pws[tid] = pw[tid];

    float uR0 = g_u[jg0], uR1 = g_u[jg0 + 1];
    float uZ0 = g_u[256 + jg0], uZ1 = g_u[256 + jg0 + 1];
    float uN0 = g_u[512 + jg0], uN1 = g_u[512 + jg0 + 1];
    float bN0 = bhh[512 + jg0], bN1 = bhh[512 + jg0 + 1];
    float postb = pb[0];
    __syncthreads();

    const float2* WR = Ws2 + (size_t)p * WS2_F2_STRIDE;
    const float2* WZ = Ws2 + (size_t)(16 + p) * WS2_F2_STRIDE;
    const float2* WN = Ws2 + (size_t)(32 + p) * WS2_F2_STRIDE;
    const float* hb = hsm + bl * 260;

    for (int t = 0; t < Tn; t++) {
        const float* gib = g_gi + ((size_t)t * 256 + b0 + bl) * 768;
        float giR0 = gib[jg0], giR1 = gib[jg0 + 1];
        float giZ0 = gib[256 + jg0], giZ1 = gib[256 + jg0 + 1];
        float giN0 = gib[512 + jg0], giN1 = gib[512 + jg0 + 1];

        ull aR0 = 0ULL, aR1 = 0ULL, aZ0 = 0ULL, aZ1 = 0ULL, aN0 = 0ULL, aN1 = 0ULL;
#pragma unroll 4
        for (int kq = 0; kq < 64; kq++) {
            float4 hv = *(const float4*)(hb + kq * 4);
            ull h0 = pk2(hv.x, hv.x), h1 = pk2(hv.y, hv.y);
            ull h2 = pk2(hv.z, hv.z), h3 = pk2(hv.w, hv.w);
            ulonglong2 r01 = *(const ulonglong2*)(WR + kq * 4);
            ulonglong2 r23 = *(const ulonglong2*)(WR + kq * 4 + 2);
            aR0 = fma2(h0, r01.x, aR0); aR1 = fma2(h1, r01.y, aR1);
            aR0 = fma2(h2, r23.x, aR0); aR1 = fma2(h3, r23.y, aR1);
            ulonglong2 z01 = *(const ulonglong2*)(WZ + kq * 4);
            ulonglong2 z23 = *(const ulonglong2*)(WZ + kq * 4 + 2);
            aZ0 = fma2(h0, z01.x, aZ0); aZ1 = fma2(h1, z01.y, aZ1);
            aZ0 = fma2(h2, z23.x, aZ0); aZ1 = fma2(h3, z23.y, aZ1);
            ulonglong2 n01 = *(const ulonglong2*)(WN + kq * 4);
            ulonglong2 n23 = *(const ulonglong2*)(WN + kq * 4 + 2);
            aN0 = fma2(h0, n01.x, aN0); aN1 = fma2(h1, n01.y, aN1);
            aN0 = fma2(h2, n23.x, aN0); aN1 = fma2(h3, n23.y, aN1);
        }
        float xr0, xr1, yr0, yr1, xz0, xz1, yz0, yz1, xn0, xn1, yn0, yn1;
        upk2(aR0, xr0, xr1); upk2(aR1, yr0, yr1);
        upk2(aZ0, xz0, xz1); upk2(aZ1, yz0, yz1);
        upk2(aN0, xn0, xn1); upk2(aN1, yn0, yn1);
        float sR0 = xr0 + yr0, sR1 = xr1 + yr1;
        float sZ0 = xz0 + yz0, sZ1 = xz1 + yz1;
        float sN0 = xn0 + yn0, sN1 = xn1 + yn1;

        float f0 = f0_s[bl];
        float h0v = hb[jg0], h1v = hb[jg0 + 1];
        float r0 = sigm(fmaf(uR0, f0, giR0) + sR0);
        float r1 = sigm(fmaf(uR1, f0, giR1) + sR1);
        float z0 = sigm(fmaf(uZ0, f0, giZ0) + sZ0);
        float z1 = sigm(fmaf(uZ1, f0, giZ1) + sZ1);
        float n0 = tanhf(fmaf(uN0, f0, giN0) + r0 * (sN0 + bN0));
        float n1 = tanhf(fmaf(uN1, f0, giN1) + r1 * (sN1 + bN1));
        float hn0 = (1.f - z0) * n0 + z0 * h0v;
        float hn1 = (1.f - z1) * n1 + z1 * h1v;

        int buf = t & 1;
        __stcg(&g_hid[buf][(b0 + bl) * 256 + jg0], hn0);
        __stcg(&g_hid[buf][(b0 + bl) * 256 + jg0 + 1], hn1);

        asm volatile("barrier.cluster.arrive.aligned;\n" ::: "memory");
        asm volatile("barrier.cluster.wait.aligned;\n" ::: "memory");

        {
            int sb = tid >> 4, sk = (tid & 15) * 16;
            const float4* src = (const float4*)&g_hid[buf][(b0 + sb) * 256 + sk];
#pragma unroll
            for (int i = 0; i < 4; i++)
                *(float4*)&hsm[sb * 260 + sk + i * 4] = __ldcg(src + i);
        }
        __syncthreads();

        // f0 = hid_new @ post_w + post_b (warp w handles batches 2w, 2w+1)
#pragma unroll
        for (int q = 0; q < 2; q++) {
            int b = 2 * w + q;
            float pacc = 0.f;
#pragma unroll
            for (int i = 0; i < 8; i++)
                pacc = fmaf(hsm[b * 260 + l * 8 + i], pws[l * 8 + i], pacc);
#pragma unroll
            for (int o = 16; o; o >>= 1) pacc += __shfl_xor_sync(0xFFFFFFFFu, pacc, o);
            if (l == 0) {
                float f = pacc + postb;
                f0_s[b] = f;
                out[(size_t)(b0 + b) * Tn + t] = f;
            }
        }
        __syncthreads();
    }
}

// ---------------- launcher ----------------
extern "C" void kernel_launch(void* const* d_in, const int* in_sizes, int n_in,
                              void* d_out, int out_size) {
    int off = (n_in >= 19) ? 1 : 0;
    const int* vw   = (const int*)d_in[off + 0];
    const int* cs   = (const int*)d_in[off + 1];
    const int* sa   = (const int*)d_in[off + 2];
    const int* ea   = (const int*)d_in[off + 3];
    const int* sap  = (const int*)d_in[off + 4];
    const int* eap  = (const int*)d_in[off + 5];
    const int* sid  = (const int*)d_in[off + 6];
    const float* hid0 = (const float*)d_in[off + 7];
    const float* pht  = (const float*)d_in[off + 8];
    const float* spt  = (const float*)d_in[off + 9];
    const float* encw = (const float*)d_in[off + 10];
    const float* encb = (const float*)d_in[off + 11];
    const float* Wih  = (const float*)d_in[off + 12];
    const float* Whh  = (const float*)d_in[off + 13];
    const float* bih  = (const float*)d_in[off + 14];
    const float* bhh  = (const float*)d_in[off + 15];
    const float* pw   = (const float*)d_in[off + 16];
    const float* pb   = (const float*)d_in[off + 17];
    float* out = (float*)d_out;

    k_pv<<<dim3(46, 3), 256>>>(pht, encw);
    k_pa<<<dim3(16, 3), 256>>>(encw);
    k_pb<<<dim3(256, 3), 256>>>(sid, spt, encw);
    k_wih<<<768, 256>>>(Wih);
    k_enc<<<dim3(Tn, Bn), 256>>>(vw, cs, sa, ea, sap, eap, encb);
    k_gemm_gi<<<dim3(12, 4096), 256>>>(bih, bhh);

    cudaFuncSetAttribute(k_gru, cudaFuncAttributeMaxDynamicSharedMemorySize, SMEM3_BYTES);
    k_gru<<<128, 256, SMEM3_BYTES>>>(hid0, Whh, bhh, pw, pb, out);
}

// round 4
// speedup vs baseline: 1.1310x; 1.1182x over previous
#include <cuda_runtime.h>
#include <cuda_bf16.h>
#include <math.h>
#include <stdint.h>

#define Tn 1024
#define Bn 256

typedef unsigned long long ull;

// ---------------- static device scratch ----------------
__device__ __align__(128) float g_pv[46 * 3 * 256];
__device__ __align__(128) float g_pa[16 * 3 * 256];
__device__ __align__(128) float g_pb[256 * 3 * 256];
__device__ __align__(128) __nv_bfloat16 g_Wb_hi[768 * 256];
__device__ __align__(128) __nv_bfloat16 g_Wb_lo[768 * 256];
__device__ __align__(128) float g_u[768];
__device__ __align__(128) __nv_bfloat16 g_h_hi[(size_t)262144 * 256];
__device__ __align__(128) __nv_bfloat16 g_h_lo[(size_t)262144 * 256];
__device__ __align__(128) float g_gi[(size_t)262144 * 768];
__device__ __align__(128) float g_hid[2][256 * 256];

__device__ __forceinline__ float sigm(float x) { return 1.f / (1.f + expf(-x)); }

// ---- packed f32x2 helpers ----
__device__ __forceinline__ ull pk2(float x, float y) {
    ull r; asm("mov.b64 %0, {%1,%2};" : "=l"(r) : "f"(x), "f"(y)); return r;
}
__device__ __forceinline__ void upk2(ull v, float& x, float& y) {
    asm("mov.b64 {%0,%1}, %2;" : "=f"(x), "=f"(y) : "l"(v));
}
__device__ __forceinline__ ull fma2(ull a, ull b, ull c) {
    ull d; asm("fma.rn.f32x2 %0, %1, %2, %3;" : "=l"(d) : "l"(a), "l"(b), "l"(c)); return d;
}

// ---------------- K_setup: fused projection tables + W_ih split ----------------
__global__ void k_setup(const float* __restrict__ ph, const float* __restrict__ spt,
                        const int* __restrict__ sid, const float* __restrict__ w,
                        const float* __restrict__ Wih) {
    int bid = blockIdx.x, c = threadIdx.x;
    if (bid < 138) {                       // phoneme proj: 46 x 3
        int p = bid / 3, k = bid % 3;
        float a = 0.f;
#pragma unroll 8
        for (int e = 0; e < 64; e++) a = fmaf(ph[p * 64 + e], w[c * 396 + e * 3 + k], a);
        g_pv[(p * 3 + k) * 256 + c] = a;
    } else if (bid < 186) {                // accent combo: 16 x 3
        int m = (bid - 138) / 3, k = (bid - 138) % 3;
        float a = 0.f;
#pragma unroll
        for (int bit = 0; bit < 4; bit++)
            if ((m >> bit) & 1) a += w[c * 396 + (64 + bit) * 3 + k];
        g_pa[(m * 3 + k) * 256 + c] = a;
    } else if (bid < 954) {                // per-batch speaker: 256 x 3
        int b = (bid - 186) / 3, k = (bid - 186) % 3;
        int s0 = sid[b];
        float a = 0.f;
#pragma unroll 8
        for (int s = 0; s < 64; s++) a = fmaf(spt[s0 * 64 + s], w[c * 396 + (68 + s) * 3 + k], a);
        g_pb[(b * 3 + k) * 256 + c] = a;
    } else {                               // W_ih repack -> bf16 hi/lo + u column
        int g = bid - 954;
        float v = Wih[g * 257 + c];
        __nv_bfloat16 hi = __float2bfloat16(v);
        __nv_bfloat16 lo = __float2bfloat16(v - __bfloat162float(hi));
        g_Wb_hi[g * 256 + c] = hi;
        g_Wb_lo[g * 256 + c] = lo;
        if (c == 0) g_u[g] = Wih[g * 257 + 256];
    }
}

// ---------------- K1: encoder (writes bf16 hi/lo directly) ----------------
__global__ void k_enc(const int* __restrict__ vw, const int* __restrict__ cs,
                      const int* __restrict__ sa, const int* __restrict__ ea,
                      const int* __restrict__ sap, const int* __restrict__ eap,
                      const float* __restrict__ encb) {
    int t = blockIdx.x, b = blockIdx.y, c = threadIdx.x;
    float a = encb[c];
#pragma unroll
    for (int k = 0; k < 3; k++) {
        int tp = t + k - 1;
        if (tp < 0 || tp >= Tn) continue;
        int o = b * Tn + tp;
        int iv = vw[o] + 1;
        int ic = cs[o] + 1;
        int ia = sa[o] + 2 * ea[o] + 4 * sap[o] + 8 * eap[o];
        a += g_pv[(iv * 3 + k) * 256 + c] + g_pv[(ic * 3 + k) * 256 + c] +
             g_pa[(ia * 3 + k) * 256 + c] + g_pb[(b * 3 + k) * 256 + c];
    }
    a = fmaxf(a, 0.f);
    __nv_bfloat16 hi = __float2bfloat16(a);
    __nv_bfloat16 lo = __float2bfloat16(a - __bfloat162float(hi));
    size_t idx = ((size_t)(t * 256 + b)) * 256 + c;
    g_h_hi[idx] = hi;
    g_h_lo[idx] = lo;
}

// ---------------- K2: tensor-core bf16-split GEMM ----------------
// gi[m][n] = sum_k h[m][k] * W[n][k];  M=262144, N=768, K=256
// CTA tile 128x128, warp tile 64x32, kc=32. 3-pass hi/lo split, fp32 accumulate.
#define ASTR 40   // smem row stride in bf16 (32 data + 8 pad)

__device__ __forceinline__ void ldsm4(uint32_t addr, uint32_t& r0, uint32_t& r1,
                                      uint32_t& r2, uint32_t& r3) {
    asm volatile("ldmatrix.sync.aligned.m8n8.x4.shared.b16 {%0,%1,%2,%3}, [%4];"
                 : "=r"(r0), "=r"(r1), "=r"(r2), "=r"(r3) : "r"(addr));
}
__device__ __forceinline__ void mma_bf16(float* c, uint32_t a0, uint32_t a1, uint32_t a2,
                                         uint32_t a3, uint32_t b0, uint32_t b1) {
    asm volatile("mma.sync.aligned.m16n8k16.row.col.f32.bf16.bf16.f32 "
                 "{%0,%1,%2,%3}, {%4,%5,%6,%7}, {%8,%9}, {%0,%1,%2,%3};"
                 : "+f"(c[0]), "+f"(c[1]), "+f"(c[2]), "+f"(c[3])
                 : "r"(a0), "r"(a1), "r"(a2), "r"(a3), "r"(b0), "r"(b1));
}

__global__ __launch_bounds__(256, 2) void k_gemm(const float* __restrict__ bih,
                                                 const float* __restrict__ bhh) {
    __shared__ __nv_bfloat16 Ah[128 * ASTR], Al[128 * ASTR];
    __shared__ __nv_bfloat16 Bh[128 * ASTR], Bl[128 * ASTR];
    int tid = threadIdx.x, lane = tid & 31, wid = tid >> 5;
    int n0 = blockIdx.x * 128;
    size_t m0 = (size_t)blockIdx.y * 128;
    int wm = (wid & 1) * 64, wn = (wid >> 1) * 32;

    float acc[4][4][4];
#pragma unroll
    for (int i = 0; i < 4; i++)
#pragma unroll
        for (int j = 0; j < 4; j++)
#pragma unroll
            for (int r = 0; r < 4; r++) acc[i][j][r] = 0.f;

    uint32_t aHiB = (uint32_t)__cvta_generic_to_shared(Ah);
    uint32_t aLoB = (uint32_t)__cvta_generic_to_shared(Al);
    uint32_t bHiB = (uint32_t)__cvta_generic_to_shared(Bh);
    uint32_t bLoB = (uint32_t)__cvta_generic_to_shared(Bl);

    for (int kt = 0; kt < 8; kt++) {
        __syncthreads();
#pragma unroll
        for (int h = 0; h < 2; h++) {
            int q = tid + h * 256;
            int row = q >> 2, c = q & 3;
            size_t gsrc = (m0 + row) * 256 + kt * 32 + c * 8;
            *(uint4*)&Ah[row * ASTR + c * 8] = *(const uint4*)&g_h_hi[gsrc];
            *(uint4*)&Al[row * ASTR + c * 8] = *(const uint4*)&g_h_lo[gsrc];
            size_t bsrc = (size_t)(n0 + row) * 256 + kt * 32 + c * 8;
            *(uint4*)&Bh[row * ASTR + c * 8] = *(const uint4*)&g_Wb_hi[bsrc];
            *(uint4*)&Bl[row * ASTR + c * 8] = *(const uint4*)&g_Wb_lo[bsrc];
        }
        __syncthreads();

#pragma unroll
        for (int s = 0; s < 2; s++) {
            // B fragments: 2 x (n16,k16) per precision
            uint32_t bh[8], bl[8];
#pragma unroll
            for (int nh = 0; nh < 2; nh++) {
                int row = wn + nh * 16 + (lane >> 4) * 8 + (lane & 7);
                int kc8 = (lane >> 3) & 1;
                uint32_t off = (uint32_t)(row * ASTR + s * 16 + kc8 * 8) * 2;
                ldsm4(bHiB + off, bh[nh * 4 + 0], bh[nh * 4 + 1], bh[nh * 4 + 2], bh[nh * 4 + 3]);
                ldsm4(bLoB + off, bl[nh * 4 + 0], bl[nh * 4 + 1], bl[nh * 4 + 2], bl[nh * 4 + 3]);
            }
#pragma unroll
            for (int mi = 0; mi < 4; mi++) {
                int row = wm + mi * 16 + ((lane >> 3) & 1) * 8 + (lane & 7);
                int kc8 = lane >> 4;
                uint32_t off = (uint32_t)(row * ASTR + s * 16 + kc8 * 8) * 2;
                uint32_t ah0, ah1, ah2, ah3, al0, al1, al2, al3;
                ldsm4(aHiB + off, ah0, ah1, ah2, ah3);
                ldsm4(aLoB + off, al0, al1, al2, al3);
#pragma unroll
                for (int ni = 0; ni < 4; ni++) {
                    uint32_t b0h = bh[ni * 2], b1h = bh[ni * 2 + 1];
                    uint32_t b0l = bl[ni * 2], b1l = bl[ni * 2 + 1];
                    mma_bf16(acc[mi][ni], ah0, ah1, ah2, ah3, b0h, b1h);
                    mma_bf16(acc[mi][ni], ah0, ah1, ah2, ah3, b0l, b1l);
                    mma_bf16(acc[mi][ni], al0, al1, al2, al3, b0h, b1h);
                }
            }
        }
    }

    // epilogue: bias add + store fp32
    float bs0[4], bs1[4];
#pragma unroll
    for (int ni = 0; ni < 4; ni++) {
        int nc = n0 + wn + ni * 8 + (lane & 3) * 2;
        bs0[ni] = bih[nc] + (nc < 512 ? bhh[nc] : 0.f);
        bs1[ni] = bih[nc + 1] + (nc + 1 < 512 ? bhh[nc + 1] : 0.f);
    }
#pragma unroll
    for (int mi = 0; mi < 4; mi++) {
#pragma unroll
        for (int ni = 0; ni < 4; ni++) {
            int r = lane >> 2;
            int nc = n0 + wn + ni * 8 + (lane & 3) * 2;
            size_t row0 = m0 + wm + mi * 16 + r;
            float2 v0 = {acc[mi][ni][0] + bs0[ni], acc[mi][ni][1] + bs1[ni]};
            float2 v1 = {acc[mi][ni][2] + bs0[ni], acc[mi][ni][3] + bs1[ni]};
            *(float2*)&g_gi[row0 * 768 + nc] = v0;
            *(float2*)&g_gi[(row0 + 8) * 768 + nc] = v1;
        }
    }
}

// ---------------- K3: persistent GRU (16 clusters x 8 CTAs) ----------------
#define WS2_F2_STRIDE 258
#define HSM_OFF (48 * WS2_F2_STRIDE * 2)
#define PWS_OFF (HSM_OFF + 16 * 260)
#define SMEM3_BYTES ((PWS_OFF + 256) * 4)

__global__ void __cluster_dims__(8, 1, 1) __launch_bounds__(256, 1)
k_gru(const float* __restrict__ hid0, const float* __restrict__ Whh,
      const float* __restrict__ bhh, const float* __restrict__ pw,
      const float* __restrict__ pb, float* __restrict__ out) {
    extern __shared__ float sm[];
    float2* Ws2 = (float2*)sm;
    float* hsm = sm + HSM_OFF;
    float* pws = sm + PWS_OFF;
    __shared__ float f0_s[16];

    int tid = threadIdx.x;
    int cid = blockIdx.x >> 3, rank = blockIdx.x & 7;
    int b0 = cid * 16, j0 = rank * 32;
    int w = tid >> 5, l = tid & 31, bl = l & 15, jsel = l >> 4;
    int p = w * 2 + jsel;
    int jg0 = j0 + 2 * p;

    for (int idx = tid; idx < 48 * 256; idx += 256) {
        int prow = idx >> 8, k = idx & 255;
        int gate = prow / 16, pp = prow % 16;
        size_t r0 = ((size_t)(gate * 256 + j0 + 2 * pp)) * 256 + k;
        float2 v;
        v.x = Whh[r0];
        v.y = Whh[r0 + 256];
        Ws2[prow * WS2_F2_STRIDE + k] = v;
    }
    {
        int sb = tid >> 4, sk = (tid & 15) * 16;
#pragma unroll
        for (int i = 0; i < 4; i++)
            *(float4*)&hsm[sb * 260 + sk + i * 4] =
                *(const float4*)&hid0[(size_t)(b0 + sb) * 256 + sk + i * 4];
    }
    if (tid < 16) f0_s[tid] = 0.f;
    pws[tid] = pw[tid];

    float uR0 = g_u[jg0], uR1 = g_u[jg0 + 1];
    float uZ0 = g_u[256 + jg0], uZ1 = g_u[256 + jg0 + 1];
    float uN0 = g_u[512 + jg0], uN1 = g_u[512 + jg0 + 1];
    float bN0 = bhh[512 + jg0], bN1 = bhh[512 + jg0 + 1];
    float postb = pb[0];
    __syncthreads();

    const float2* WR = Ws2 + (size_t)p * WS2_F2_STRIDE;
    const float2* WZ = Ws2 + (size_t)(16 + p) * WS2_F2_STRIDE;
    const float2* WN = Ws2 + (size_t)(32 + p) * WS2_F2_STRIDE;
    const float* hb = hsm + bl * 260;

    for (int t = 0; t < Tn; t++) {
        const float* gib = g_gi + ((size_t)t * 256 + b0 + bl) * 768;
        float giR0 = gib[jg0], giR1 = gib[jg0 + 1];
        float giZ0 = gib[256 + jg0], giZ1 = gib[256 + jg0 + 1];
        float giN0 = gib[512 + jg0], giN1 = gib[512 + jg0 + 1];

        ull aR0 = 0ULL, aR1 = 0ULL, aZ0 = 0ULL, aZ1 = 0ULL, aN0 = 0ULL, aN1 = 0ULL;
#pragma unroll 4
        for (int kq = 0; kq < 64; kq++) {
            float4 hv = *(const float4*)(hb + kq * 4);
            ull h0 = pk2(hv.x, hv.x), h1 = pk2(hv.y, hv.y);
            ull h2 = pk2(hv.z, hv.z), h3 = pk2(hv.w, hv.w);
            ulonglong2 r01 = *(const ulonglong2*)(WR + kq * 4);
            ulonglong2 r23 = *(const ulonglong2*)(WR + kq * 4 + 2);
            aR0 = fma2(h0, r01.x, aR0); aR1 = fma2(h1, r01.y, aR1);
            aR0 = fma2(h2, r23.x, aR0); aR1 = fma2(h3, r23.y, aR1);
            ulonglong2 z01 = *(const ulonglong2*)(WZ + kq * 4);
            ulonglong2 z23 = *(const ulonglong2*)(WZ + kq * 4 + 2);
            aZ0 = fma2(h0, z01.x, aZ0); aZ1 = fma2(h1, z01.y, aZ1);
            aZ0 = fma2(h2, z23.x, aZ0); aZ1 = fma2(h3, z23.y, aZ1);
            ulonglong2 n01 = *(const ulonglong2*)(WN + kq * 4);
            ulonglong2 n23 = *(const ulonglong2*)(WN + kq * 4 + 2);
            aN0 = fma2(h0, n01.x, aN0); aN1 = fma2(h1, n01.y, aN1);
            aN0 = fma2(h2, n23.x, aN0); aN1 = fma2(h3, n23.y, aN1);
        }
        float xr0, xr1, yr0, yr1, xz0, xz1, yz0, yz1, xn0, xn1, yn0, yn1;
        upk2(aR0, xr0, xr1); upk2(aR1, yr0, yr1);
        upk2(aZ0, xz0, xz1); upk2(aZ1, yz0, yz1);
        upk2(aN0, xn0, xn1); upk2(aN1, yn0, yn1);
        float sR0 = xr0 + yr0, sR1 = xr1 + yr1;
        float sZ0 = xz0 + yz0, sZ1 = xz1 + yz1;
        float sN0 = xn0 + yn0, sN1 = xn1 + yn1;

        float f0 = f0_s[bl];
        float h0v = hb[jg0], h1v = hb[jg0 + 1];
        float r0 = sigm(fmaf(uR0, f0, giR0) + sR0);
        float r1 = sigm(fmaf(uR1, f0, giR1) + sR1);
        float z0 = sigm(fmaf(uZ0, f0, giZ0) + sZ0);
        float z1 = sigm(fmaf(uZ1, f0, giZ1) + sZ1);
        float n0 = tanhf(fmaf(uN0, f0, giN0) + r0 * (sN0 + bN0));
        float n1 = tanhf(fmaf(uN1, f0, giN1) + r1 * (sN1 + bN1));
        float hn0 = (1.f - z0) * n0 + z0 * h0v;
        float hn1 = (1.f - z1) * n1 + z1 * h1v;

        int buf = t & 1;
        __stcg(&g_hid[buf][(b0 + bl) * 256 + jg0], hn0);
        __stcg(&g_hid[buf][(b0 + bl) * 256 + jg0 + 1], hn1);

        asm volatile("barrier.cluster.arrive.aligned;\n" ::: "memory");
        asm volatile("barrier.cluster.wait.aligned;\n" ::: "memory");

        {
            int sb = tid >> 4, sk = (tid & 15) * 16;
            const float4* src = (const float4*)&g_hid[buf][(b0 + sb) * 256 + sk];
#pragma unroll
            for (int i = 0; i < 4; i++)
                *(float4*)&hsm[sb * 260 + sk + i * 4] = __ldcg(src + i);
        }
        __syncthreads();

#pragma unroll
        for (int q = 0; q < 2; q++) {
            int b = 2 * w + q;
            float pacc = 0.f;
#pragma unroll
            for (int i = 0; i < 8; i++)
                pacc = fmaf(hsm[b * 260 + l * 8 + i], pws[l * 8 + i], pacc);
#pragma unroll
            for (int o = 16; o; o >>= 1) pacc += __shfl_xor_sync(0xFFFFFFFFu, pacc, o);
            if (l == 0) {
                float f = pacc + postb;
                f0_s[b] = f;
                out[(size_t)(b0 + b) * Tn + t] = f;
            }
        }
        __syncthreads();
    }
}

// ---------------- launcher ----------------
extern "C" void kernel_launch(void* const* d_in, const int* in_sizes, int n_in,
                              void* d_out, int out_size) {
    int off = (n_in >= 19) ? 1 : 0;
    const int* vw   = (const int*)d_in[off + 0];
    const int* cs   = (const int*)d_in[off + 1];
    const int* sa   = (const int*)d_in[off + 2];
    const int* ea   = (const int*)d_in[off + 3];
    const int* sap  = (const int*)d_in[off + 4];
    const int* eap  = (const int*)d_in[off + 5];
    const int* sid  = (const int*)d_in[off + 6];
    const float* hid0 = (const float*)d_in[off + 7];
    const float* pht  = (const float*)d_in[off + 8];
    const float* spt  = (const float*)d_in[off + 9];
    const float* encw = (const float*)d_in[off + 10];
    const float* encb = (const float*)d_in[off + 11];
    const float* Wih  = (const float*)d_in[off + 12];
    const float* Whh  = (const float*)d_in[off + 13];
    const float* bih  = (const float*)d_in[off + 14];
    const float* bhh  = (const float*)d_in[off + 15];
    const float* pw   = (const float*)d_in[off + 16];
    const float* pb   = (const float*)d_in[off + 17];
    float* out = (float*)d_out;

    k_setup<<<1722, 256>>>(pht, spt, sid, encw, Wih);
    k_enc<<<dim3(Tn, Bn), 256>>>(vw, cs, sa, ea, sap, eap, encb);
    k_gemm<<<dim3(6, 2048), 256>>>(bih, bhh);

    cudaFuncSetAttribute(k_gru, cudaFuncAttributeMaxDynamicSharedMemorySize, SMEM3_BYTES);
    k_gru<<<128, 256, SMEM3_BYTES>>>(hid0, Whh, bhh, pw, pb, out);
}

// round 5
// speedup vs baseline: 3.1682x; 2.8012x over previous
#include <cuda_runtime.h>
#include <cuda_bf16.h>
#include <math.h>
#include <stdint.h>

#define Tn 1024
#define Bn 256

typedef unsigned long long ull;

// ---------------- static device scratch ----------------
__device__ __align__(128) float g_pv[46 * 3 * 256];
__device__ __align__(128) float g_pa[16 * 3 * 256];
__device__ __align__(128) float g_pb[256 * 3 * 256];
__device__ __align__(128) __nv_bfloat16 g_Wb_hi[768 * 256];
__device__ __align__(128) __nv_bfloat16 g_Wb_lo[768 * 256];
__device__ __align__(128) float g_u[768];
__device__ __align__(128) __nv_bfloat16 g_h_hi[(size_t)262144 * 256];
__device__ __align__(128) __nv_bfloat16 g_h_lo[(size_t)262144 * 256];
__device__ __align__(128) float g_gi[(size_t)262144 * 768];
__device__ __align__(128) uint32_t g_hx[2][256 * 256];   // packed (bf16 hi | lo<<16) hidden
__device__ __align__(128) float g_f0p[2][128 * 8];       // per-CTA f0 partials

__device__ __forceinline__ float sigm(float x) { return 1.f / (1.f + expf(-x)); }

__device__ __forceinline__ uint32_t prmt(uint32_t a, uint32_t b, uint32_t s) {
    uint32_t d; asm("prmt.b32 %0,%1,%2,%3;" : "=r"(d) : "r"(a), "r"(b), "r"(s)); return d;
}

// ---------------- K_setup ----------------
__global__ void k_setup(const float* __restrict__ ph, const float* __restrict__ spt,
                        const int* __restrict__ sid, const float* __restrict__ w,
                        const float* __restrict__ Wih) {
    int bid = blockIdx.x, c = threadIdx.x;
    if (bid < 138) {
        int p = bid / 3, k = bid % 3;
        float a = 0.f;
#pragma unroll 8
        for (int e = 0; e < 64; e++) a = fmaf(ph[p * 64 + e], w[c * 396 + e * 3 + k], a);
        g_pv[(p * 3 + k) * 256 + c] = a;
    } else if (bid < 186) {
        int m = (bid - 138) / 3, k = (bid - 138) % 3;
        float a = 0.f;
#pragma unroll
        for (int bit = 0; bit < 4; bit++)
            if ((m >> bit) & 1) a += w[c * 396 + (64 + bit) * 3 + k];
        g_pa[(m * 3 + k) * 256 + c] = a;
    } else if (bid < 954) {
        int b = (bid - 186) / 3, k = (bid - 186) % 3;
        int s0 = sid[b];
        float a = 0.f;
#pragma unroll 8
        for (int s = 0; s < 64; s++) a = fmaf(spt[s0 * 64 + s], w[c * 396 + (68 + s) * 3 + k], a);
        g_pb[(b * 3 + k) * 256 + c] = a;
    } else {
        int g = bid - 954;
        float v = Wih[g * 257 + c];
        __nv_bfloat16 hi = __float2bfloat16(v);
        __nv_bfloat16 lo = __float2bfloat16(v - __bfloat162float(hi));
        g_Wb_hi[g * 256 + c] = hi;
        g_Wb_lo[g * 256 + c] = lo;
        if (c == 0) g_u[g] = Wih[g * 257 + 256];
    }
}

// ---------------- K1: encoder ----------------
__global__ void k_enc(const int* __restrict__ vw, const int* __restrict__ cs,
                      const int* __restrict__ sa, const int* __restrict__ ea,
                      const int* __restrict__ sap, const int* __restrict__ eap,
                      const float* __restrict__ encb) {
    int t = blockIdx.x, b = blockIdx.y, c = threadIdx.x;
    float a = encb[c];
#pragma unroll
    for (int k = 0; k < 3; k++) {
        int tp = t + k - 1;
        if (tp < 0 || tp >= Tn) continue;
        int o = b * Tn + tp;
        int iv = vw[o] + 1;
        int ic = cs[o] + 1;
        int ia = sa[o] + 2 * ea[o] + 4 * sap[o] + 8 * eap[o];
        a += g_pv[(iv * 3 + k) * 256 + c] + g_pv[(ic * 3 + k) * 256 + c] +
             g_pa[(ia * 3 + k) * 256 + c] + g_pb[(b * 3 + k) * 256 + c];
    }
    a = fmaxf(a, 0.f);
    __nv_bfloat16 hi = __float2bfloat16(a);
    __nv_bfloat16 lo = __float2bfloat16(a - __bfloat162float(hi));
    size_t idx = ((size_t)(t * 256 + b)) * 256 + c;
    g_h_hi[idx] = hi;
    g_h_lo[idx] = lo;
}

// ---------------- mma helpers ----------------
__device__ __forceinline__ void ldsm4(uint32_t addr, uint32_t& r0, uint32_t& r1,
                                      uint32_t& r2, uint32_t& r3) {
    asm volatile("ldmatrix.sync.aligned.m8n8.x4.shared.b16 {%0,%1,%2,%3}, [%4];"
                 : "=r"(r0), "=r"(r1), "=r"(r2), "=r"(r3) : "r"(addr));
}
__device__ __forceinline__ void mma_bf16(float* c, uint32_t a0, uint32_t a1, uint32_t a2,
                                         uint32_t a3, uint32_t b0, uint32_t b1) {
    asm volatile("mma.sync.aligned.m16n8k16.row.col.f32.bf16.bf16.f32 "
                 "{%0,%1,%2,%3}, {%4,%5,%6,%7}, {%8,%9}, {%0,%1,%2,%3};"
                 : "+f"(c[0]), "+f"(c[1]), "+f"(c[2]), "+f"(c[3])
                 : "r"(a0), "r"(a1), "r"(a2), "r"(a3), "r"(b0), "r"(b1));
}

// ---------------- K2: tensor-core bf16-split GEMM (unchanged) ----------------
#define ASTR 40

__global__ __launch_bounds__(256, 2) void k_gemm(const float* __restrict__ bih,
                                                 const float* __restrict__ bhh) {
    __shared__ __nv_bfloat16 Ah[128 * ASTR], Al[128 * ASTR];
    __shared__ __nv_bfloat16 Bh[128 * ASTR], Bl[128 * ASTR];
    int tid = threadIdx.x, lane = tid & 31, wid = tid >> 5;
    int n0 = blockIdx.x * 128;
    size_t m0 = (size_t)blockIdx.y * 128;
    int wm = (wid & 1) * 64, wn = (wid >> 1) * 32;

    float acc[4][4][4];
#pragma unroll
    for (int i = 0; i < 4; i++)
#pragma unroll
        for (int j = 0; j < 4; j++)
#pragma unroll
            for (int r = 0; r < 4; r++) acc[i][j][r] = 0.f;

    uint32_t aHiB = (uint32_t)__cvta_generic_to_shared(Ah);
    uint32_t aLoB = (uint32_t)__cvta_generic_to_shared(Al);
    uint32_t bHiB = (uint32_t)__cvta_generic_to_shared(Bh);
    uint32_t bLoB = (uint32_t)__cvta_generic_to_shared(Bl);

    for (int kt = 0; kt < 8; kt++) {
        __syncthreads();
#pragma unroll
        for (int h = 0; h < 2; h++) {
            int q = tid + h * 256;
            int row = q >> 2, c = q & 3;
            size_t gsrc = (m0 + row) * 256 + kt * 32 + c * 8;
            *(uint4*)&Ah[row * ASTR + c * 8] = *(const uint4*)&g_h_hi[gsrc];
            *(uint4*)&Al[row * ASTR + c * 8] = *(const uint4*)&g_h_lo[gsrc];
            size_t bsrc = (size_t)(n0 + row) * 256 + kt * 32 + c * 8;
            *(uint4*)&Bh[row * ASTR + c * 8] = *(const uint4*)&g_Wb_hi[bsrc];
            *(uint4*)&Bl[row * ASTR + c * 8] = *(const uint4*)&g_Wb_lo[bsrc];
        }
        __syncthreads();

#pragma unroll
        for (int s = 0; s < 2; s++) {
            uint32_t bh[8], bl[8];
#pragma unroll
            for (int nh = 0; nh < 2; nh++) {
                int row = wn + nh * 16 + (lane >> 4) * 8 + (lane & 7);
                int kc8 = (lane >> 3) & 1;
                uint32_t off = (uint32_t)(row * ASTR + s * 16 + kc8 * 8) * 2;
                ldsm4(bHiB + off, bh[nh * 4 + 0], bh[nh * 4 + 1], bh[nh * 4 + 2], bh[nh * 4 + 3]);
                ldsm4(bLoB + off, bl[nh * 4 + 0], bl[nh * 4 + 1], bl[nh * 4 + 2], bl[nh * 4 + 3]);
            }
#pragma unroll
            for (int mi = 0; mi < 4; mi++) {
                int row = wm + mi * 16 + ((lane >> 3) & 1) * 8 + (lane & 7);
                int kc8 = lane >> 4;
                uint32_t off = (uint32_t)(row * ASTR + s * 16 + kc8 * 8) * 2;
                uint32_t ah0, ah1, ah2, ah3, al0, al1, al2, al3;
                ldsm4(aHiB + off, ah0, ah1, ah2, ah3);
                ldsm4(aLoB + off, al0, al1, al2, al3);
#pragma unroll
                for (int ni = 0; ni < 4; ni++) {
                    uint32_t b0h = bh[ni * 2], b1h = bh[ni * 2 + 1];
                    uint32_t b0l = bl[ni * 2], b1l = bl[ni * 2 + 1];
                    mma_bf16(acc[mi][ni], ah0, ah1, ah2, ah3, b0h, b1h);
                    mma_bf16(acc[mi][ni], ah0, ah1, ah2, ah3, b0l, b1l);
                    mma_bf16(acc[mi][ni], al0, al1, al2, al3, b0h, b1h);
                }
            }
        }
    }

    float bs0[4], bs1[4];
#pragma unroll
    for (int ni = 0; ni < 4; ni++) {
        int nc = n0 + wn + ni * 8 + (lane & 3) * 2;
        bs0[ni] = bih[nc] + (nc < 512 ? bhh[nc] : 0.f);
        bs1[ni] = bih[nc + 1] + (nc + 1 < 512 ? bhh[nc + 1] : 0.f);
    }
#pragma unroll
    for (int mi = 0; mi < 4; mi++) {
#pragma unroll
        for (int ni = 0; ni < 4; ni++) {
            int r = lane >> 2;
            int nc = n0 + wn + ni * 8 + (lane & 3) * 2;
            size_t row0 = m0 + wm + mi * 16 + r;
            float2 v0 = {acc[mi][ni][0] + bs0[ni], acc[mi][ni][1] + bs1[ni]};
            float2 v1 = {acc[mi][ni][2] + bs0[ni], acc[mi][ni][3] + bs1[ni]};
            *(float2*)&g_gi[row0 * 768 + nc] = v0;
            *(float2*)&g_gi[(row0 + 8) * 768 + nc] = v1;
        }
    }
}

// ---------------- K3: tensor-core GRU (32 clusters x 4 CTAs) ----------------
// CTA: 8 batches (m, padded to 16) x 64 cols -> n=192 gate rows, k=256.
// SMEM layout (bytes):
#define BSTR 264                                  // bf16 row stride (256+8)
#define OFF_BHI 0
#define OFF_BLO (192 * BSTR * 2)                  // 101376
#define OFF_AHI (OFF_BLO + 192 * BSTR * 2)        // 202752
#define OFF_ALO (OFF_AHI + 16 * BSTR * 2)         // 211200
#define OFF_PRE (OFF_ALO + 16 * BSTR * 2)         // 219648  s_pre[192][9] f32
#define OFF_SW  (OFF_PRE + 192 * 9 * 4)           // 226560  s_w[8][8] f32
#define OFF_F0  (OFF_SW + 256)                    // 226816  f0_s[8]
#define SMEM3_BYTES (OFF_F0 + 32)                 // 226848

__global__ void __cluster_dims__(4, 1, 1) __launch_bounds__(256, 1)
k_gru(const float* __restrict__ hid0, const float* __restrict__ Whh,
      const float* __restrict__ bhh, const float* __restrict__ pw,
      const float* __restrict__ pb, float* __restrict__ out) {
    extern __shared__ char smem[];
    __nv_bfloat16* Bhi = (__nv_bfloat16*)(smem + OFF_BHI);
    __nv_bfloat16* Blo = (__nv_bfloat16*)(smem + OFF_BLO);
    __nv_bfloat16* Ahi = (__nv_bfloat16*)(smem + OFF_AHI);
    __nv_bfloat16* Alo = (__nv_bfloat16*)(smem + OFF_ALO);
    float* s_pre = (float*)(smem + OFF_PRE);
    float* s_w = (float*)(smem + OFF_SW);
    float* f0s = (float*)(smem + OFF_F0);

    int tid = threadIdx.x, lane = tid & 31, wid = tid >> 5;
    int cid = blockIdx.x >> 2, rank = blockIdx.x & 3;
    int b0 = cid * 8, gj0 = rank * 64;

    // --- load W_hh slice as bf16 hi/lo (rows n = gate*64 + jloc) ---
    for (int idx = tid; idx < 192 * 256; idx += 256) {
        int n = idx >> 8, k = idx & 255;
        int gate = n >> 6, jloc = n & 63;
        float v = Whh[((size_t)(gate * 256 + gj0 + jloc)) * 256 + k];
        __nv_bfloat16 hi = __float2bfloat16(v);
        Bhi[n * BSTR + k] = hi;
        Blo[n * BSTR + k] = __float2bfloat16(v - __bfloat162float(hi));
    }
    // --- zero A tiles (incl pad rows 8..15) ---
    for (int idx = tid; idx < 16 * BSTR; idx += 256) {
        Ahi[idx] = __float2bfloat16(0.f);
        Alo[idx] = __float2bfloat16(0.f);
    }
    __syncthreads();
    // --- A init from hid0 ---
    {
        int b = tid >> 5, kg = (tid & 31) * 8;
#pragma unroll
        for (int i = 0; i < 8; i++) {
            float v = hid0[(size_t)(b0 + b) * 256 + kg + i];
            __nv_bfloat16 hi = __float2bfloat16(v);
            Ahi[b * BSTR + kg + i] = hi;
            Alo[b * BSTR + kg + i] = __float2bfloat16(v - __bfloat162float(hi));
        }
    }
    if (tid < 8) f0s[tid] = 0.f;

    // --- per-thread persistent items: (bi, jA) and (bi, jB) ---
    int bi = tid & 7, jA = tid >> 3, jB = jA + 32;
    float uR_A = g_u[gj0 + jA], uR_B = g_u[gj0 + jB];
    float uZ_A = g_u[256 + gj0 + jA], uZ_B = g_u[256 + gj0 + jB];
    float uN_A = g_u[512 + gj0 + jA], uN_B = g_u[512 + gj0 + jB];
    float bN_A = bhh[512 + gj0 + jA], bN_B = bhh[512 + gj0 + jB];
    float pw_A = pw[gj0 + jA], pw_B = pw[gj0 + jB];
    float postb = pb[0];
    float hA = hid0[(size_t)(b0 + bi) * 256 + gj0 + jA];
    float hB = hid0[(size_t)(b0 + bi) * 256 + gj0 + jB];
    __syncthreads();

    // --- mma group assignment: warps 0-3 -> 2 groups, 4-7 -> 1 group ---
    int g0 = (wid < 4) ? 2 * wid : (wid + 4);
    int ng = (wid < 4) ? 2 : 1;

    uint32_t smemB = (uint32_t)__cvta_generic_to_shared(smem);
    int aRow = ((lane >> 3) & 1) * 8 + (lane & 7);
    uint32_t aOff = (uint32_t)(aRow * BSTR + (lane >> 4) * 8) * 2;
    uint32_t aHiA = smemB + OFF_AHI + aOff;
    uint32_t aLoA = smemB + OFF_ALO + aOff;
    int bRow0 = g0 * 16 + (lane >> 4) * 8 + (lane & 7);
    uint32_t bOff0 = (uint32_t)(bRow0 * BSTR + ((lane >> 3) & 1) * 8) * 2;
    uint32_t bHiA0 = smemB + OFF_BHI + bOff0;
    uint32_t bLoA0 = smemB + OFF_BLO + bOff0;
    uint32_t bHiA1 = bHiA0 + 16 * BSTR * 2;   // group g0+1
    uint32_t bLoA1 = bLoA0 + 16 * BSTR * 2;

    int cRow = lane >> 2;                      // batch 0..7
    int cCol0 = (lane & 3) * 2;

    for (int t = 0; t < Tn; t++) {
        int buf = t & 1;
        // prefetch gi (consumed after mma)
        size_t gbase = ((size_t)t * 256 + b0 + bi) * 768;
        float giR_A = g_gi[gbase + gj0 + jA], giR_B = g_gi[gbase + gj0 + jB];
        float giZ_A = g_gi[gbase + 256 + gj0 + jA], giZ_B = g_gi[gbase + 256 + gj0 + jB];
        float giN_A = g_gi[gbase + 512 + gj0 + jA], giN_B = g_gi[gbase + 512 + gj0 + jB];

        float acc[2][2][4];
#pragma unroll
        for (int g = 0; g < 2; g++)
#pragma unroll
            for (int ti = 0; ti < 2; ti++)
#pragma unroll
                for (int r = 0; r < 4; r++) acc[g][ti][r] = 0.f;

#pragma unroll 4
        for (int c16 = 0; c16 < 16; c16++) {
            uint32_t ko = c16 * 32;
            uint32_t ah0, ah1, ah2, ah3, al0, al1, al2, al3;
            ldsm4(aHiA + ko, ah0, ah1, ah2, ah3);
            ldsm4(aLoA + ko, al0, al1, al2, al3);
            {
                uint32_t bh0, bh1, bh2, bh3, bl0, bl1, bl2, bl3;
                ldsm4(bHiA0 + ko, bh0, bh1, bh2, bh3);
                ldsm4(bLoA0 + ko, bl0, bl1, bl2, bl3);
                mma_bf16(acc[0][0], ah0, ah1, ah2, ah3, bh0, bh1);
                mma_bf16(acc[0][0], ah0, ah1, ah2, ah3, bl0, bl1);
                mma_bf16(acc[0][0], al0, al1, al2, al3, bh0, bh1);
                mma_bf16(acc[0][1], ah0, ah1, ah2, ah3, bh2, bh3);
                mma_bf16(acc[0][1], ah0, ah1, ah2, ah3, bl2, bl3);
                mma_bf16(acc[0][1], al0, al1, al2, al3, bh2, bh3);
            }
            if (ng == 2) {
                uint32_t bh0, bh1, bh2, bh3, bl0, bl1, bl2, bl3;
                ldsm4(bHiA1 + ko, bh0, bh1, bh2, bh3);
                ldsm4(bLoA1 + ko, bl0, bl1, bl2, bl3);
                mma_bf16(acc[1][0], ah0, ah1, ah2, ah3, bh0, bh1);
                mma_bf16(acc[1][0], ah0, ah1, ah2, ah3, bl0, bl1);
                mma_bf16(acc[1][0], al0, al1, al2, al3, bh0, bh1);
                mma_bf16(acc[1][1], ah0, ah1, ah2, ah3, bh2, bh3);
                mma_bf16(acc[1][1], ah0, ah1, ah2, ah3, bl2, bl3);
                mma_bf16(acc[1][1], al0, al1, al2, al3, bh2, bh3);
            }
        }

        // scatter pre-activations to s_pre[n][b]
#pragma unroll
        for (int g = 0; g < 2; g++) {
            if (g >= ng) break;
            int nb = (g ? g0 + 1 : g0) * 16;
#pragma unroll
            for (int ti = 0; ti < 2; ti++) {
                int n = nb + ti * 8 + cCol0;
                s_pre[n * 9 + cRow] = acc[g][ti][0];
                s_pre[(n + 1) * 9 + cRow] = acc[g][ti][1];
            }
        }
        __syncthreads();

        // gate combine for 2 items
        float f0 = f0s[bi];
        float aR_A = s_pre[jA * 9 + bi], aZ_A = s_pre[(64 + jA) * 9 + bi], aN_A = s_pre[(128 + jA) * 9 + bi];
        float aR_B = s_pre[jB * 9 + bi], aZ_B = s_pre[(64 + jB) * 9 + bi], aN_B = s_pre[(128 + jB) * 9 + bi];
        float rA = sigm(fmaf(uR_A, f0, giR_A) + aR_A);
        float zA = sigm(fmaf(uZ_A, f0, giZ_A) + aZ_A);
        float nA = tanhf(fmaf(uN_A, f0, giN_A) + rA * (aN_A + bN_A));
        float hnA = (1.f - zA) * nA + zA * hA;
        float rB = sigm(fmaf(uR_B, f0, giR_B) + aR_B);
        float zB = sigm(fmaf(uZ_B, f0, giZ_B) + aZ_B);
        float nB = tanhf(fmaf(uN_B, f0, giN_B) + rB * (aN_B + bN_B));
        float hnB = (1.f - zB) * nB + zB * hB;
        hA = hnA; hB = hnB;

        // pack + exchange via L2
        {
            __nv_bfloat16 hiA = __float2bfloat16(hnA);
            __nv_bfloat16 loA = __float2bfloat16(hnA - __bfloat162float(hiA));
            uint32_t pA = (uint32_t)__bfloat16_as_ushort(hiA) |
                          ((uint32_t)__bfloat16_as_ushort(loA) << 16);
            __nv_bfloat16 hiB = __float2bfloat16(hnB);
            __nv_bfloat16 loB = __float2bfloat16(hnB - __bfloat162float(hiB));
            uint32_t pB = (uint32_t)__bfloat16_as_ushort(hiB) |
                          ((uint32_t)__bfloat16_as_ushort(loB) << 16);
            __stcg(&g_hx[buf][(b0 + bi) * 256 + gj0 + jA], pA);
            __stcg(&g_hx[buf][(b0 + bi) * 256 + gj0 + jB], pB);
        }

        // per-CTA f0 partial
        float pf = fmaf(hnA, pw_A, hnB * pw_B);
        pf += __shfl_xor_sync(0xFFFFFFFFu, pf, 8);
        pf += __shfl_xor_sync(0xFFFFFFFFu, pf, 16);
        if (lane < 8) s_w[wid * 8 + lane] = pf;
        __syncthreads();
        if (tid < 8) {
            float s = 0.f;
#pragma unroll
            for (int w2 = 0; w2 < 8; w2++) s += s_w[w2 * 8 + tid];
            __stcg(&g_f0p[buf][(cid * 4 + rank) * 8 + tid], s);
        }

        asm volatile("barrier.cluster.arrive.aligned;\n" ::: "memory");
        asm volatile("barrier.cluster.wait.aligned;\n" ::: "memory");

        // restage A from packed exchange
        {
            int b = tid >> 5, kg = (tid & 31) * 8;
            const uint4* src = (const uint4*)&g_hx[buf][(b0 + b) * 256 + kg];
            uint4 u0 = __ldcg(src);
            uint4 u1 = __ldcg(src + 1);
            uint4 hi, lo;
            hi.x = prmt(u0.x, u0.y, 0x5410); hi.y = prmt(u0.z, u0.w, 0x5410);
            hi.z = prmt(u1.x, u1.y, 0x5410); hi.w = prmt(u1.z, u1.w, 0x5410);
            lo.x = prmt(u0.x, u0.y, 0x7632); lo.y = prmt(u0.z, u0.w, 0x7632);
            lo.z = prmt(u1.x, u1.y, 0x7632); lo.w = prmt(u1.z, u1.w, 0x7632);
            *(uint4*)&Ahi[b * BSTR + kg] = hi;
            *(uint4*)&Alo[b * BSTR + kg] = lo;
        }
        if (tid < 8) {
            float s = postb;
#pragma unroll
            for (int r = 0; r < 4; r++) s += __ldcg(&g_f0p[buf][(cid * 4 + r) * 8 + tid]);
            f0s[tid] = s;
            if (rank == 0) out[(size_t)(b0 + tid) * Tn + t] = s;
        }
        __syncthreads();
    }
}

// ---------------- launcher ----------------
extern "C" void kernel_launch(void* const* d_in, const int* in_sizes, int n_in,
                              void* d_out, int out_size) {
    int off = (n_in >= 19) ? 1 : 0;
    const int* vw   = (const int*)d_in[off + 0];
    const int* cs   = (const int*)d_in[off + 1];
    const int* sa   = (const int*)d_in[off + 2];
    const int* ea   = (const int*)d_in[off + 3];
    const int* sap  = (const int*)d_in[off + 4];
    const int* eap  = (const int*)d_in[off + 5];
    const int* sid  = (const int*)d_in[off + 6];
    const float* hid0 = (const float*)d_in[off + 7];
    const float* pht  = (const float*)d_in[off + 8];
    const float* spt  = (const float*)d_in[off + 9];
    const float* encw = (const float*)d_in[off + 10];
    const float* encb = (const float*)d_in[off + 11];
    const float* Wih  = (const float*)d_in[off + 12];
    const float* Whh  = (const float*)d_in[off + 13];
    const float* bih  = (const float*)d_in[off + 14];
    const float* bhh  = (const float*)d_in[off + 15];
    const float* pw   = (const float*)d_in[off + 16];
    const float* pb   = (const float*)d_in[off + 17];
    float* out = (float*)d_out;

    k_setup<<<1722, 256>>>(pht, spt, sid, encw, Wih);
    k_enc<<<dim3(Tn, Bn), 256>>>(vw, cs, sa, ea, sap, eap, encb);
    k_gemm<<<dim3(6, 2048), 256>>>(bih, bhh);

    cudaFuncSetAttribute(k_gru, cudaFuncAttributeMaxDynamicSharedMemorySize, SMEM3_BYTES);
    k_gru<<<128, 256, SMEM3_BYTES>>>(hid0, Whh, bhh, pw, pb, out);
}